// round 2
// baseline (speedup 1.0000x reference)
#include <cuda_runtime.h>

// Problem dims (fixed per reference)
#define BQ 8
#define LQ 4096
#define HQ 768
#define PQ 256
#define ROWS (BQ*LQ)        // 32768
#define LC 64               // scan chunk length
#define NCHUNK (LQ/LC)      // 64

// ---------------- scratch (__device__ globals; no allocation allowed) ------
__device__ float g_Wcat[HQ * 3 * PQ];            // [768][768] K-major
__device__ float g_Ccat[2 * PQ * HQ];            // [512][768] K-major
__device__ float g_Y[(size_t)ROWS * 3 * PQ];     // [32768][768]: dt-logit | Bu_re | Bu_im
__device__ float g_X[(size_t)ROWS * 2 * PQ];     // [32768][512]: x_re | x_im
__device__ float g_chunk[BQ * PQ * NCHUNK * 8];  // per-chunk (A 2x2, b complex2)
__device__ float g_carry[BQ * PQ * NCHUNK * 4];  // carry-in state per chunk

// ---------------- prep: pack weight matrices -------------------------------
__global__ void prep_wcat(const float* __restrict__ W_dt,
                          const float* __restrict__ B_re,
                          const float* __restrict__ B_im) {
    int idx = blockIdx.x * blockDim.x + threadIdx.x;
    if (idx >= HQ * 3 * PQ) return;
    int k = idx / (3 * PQ);   // h
    int n = idx % (3 * PQ);
    float v;
    if (n < PQ)            v = W_dt[k * PQ + n];            // W_dt[h,p]
    else if (n < 2 * PQ)   v = B_re[(n - PQ) * HQ + k];     // B_re[p,h]
    else                   v = B_im[(n - 2 * PQ) * HQ + k]; // B_im[p,h]
    g_Wcat[idx] = v;
}

__global__ void prep_ccat(const float* __restrict__ C_re,
                          const float* __restrict__ C_im) {
    int idx = blockIdx.x * blockDim.x + threadIdx.x;
    if (idx >= 2 * PQ * HQ) return;
    int k = idx / HQ;
    int n = idx % HQ;
    float v;
    if (k < PQ) v =  C_re[n * PQ + k];          // C_re[h,p]
    else        v = -C_im[n * PQ + (k - PQ)];   // -C_im[h,p]
    g_Ccat[idx] = v;
}

// ---------------- tiled SGEMM: C = A[M,K] @ B[K,N] (+ D.*U epilogue) -------
// BM=BN=128, BK=16, 256 threads, 8x8 microtile. M%128==0, N%128==0, K%16==0.
template<bool EPI>
__global__ __launch_bounds__(256)
void sgemm(const float* __restrict__ A, const float* __restrict__ B,
           float* __restrict__ C, int M, int N, int K,
           const float* __restrict__ Dv, const float* __restrict__ U) {
    __shared__ float As[16][128];
    __shared__ float Bs[16][128];
    const int tid  = threadIdx.x;
    const int row0 = blockIdx.y * 128;
    const int col0 = blockIdx.x * 128;
    const int tRow = tid >> 4;     // 0..15
    const int tCol = tid & 15;     // 0..15

    float acc[8][8];
#pragma unroll
    for (int i = 0; i < 8; i++)
#pragma unroll
        for (int j = 0; j < 8; j++) acc[i][j] = 0.f;

    for (int kt = 0; kt < K; kt += 16) {
        // load A tile (128x16), store transposed As[k][m]
#pragma unroll
        for (int i = 0; i < 2; i++) {
            int lin = tid + i * 256;           // 0..511 float4 slots
            int r   = lin >> 2;                // 0..127
            int c4  = (lin & 3) << 2;          // 0,4,8,12
            float4 v = *(const float4*)(A + (size_t)(row0 + r) * K + kt + c4);
            As[c4 + 0][r] = v.x; As[c4 + 1][r] = v.y;
            As[c4 + 2][r] = v.z; As[c4 + 3][r] = v.w;
        }
        // load B tile (16x128)
#pragma unroll
        for (int i = 0; i < 2; i++) {
            int lin = tid + i * 256;
            int r   = lin >> 5;                // 0..15
            int c4  = (lin & 31) << 2;         // 0..124
            *(float4*)&Bs[r][c4] =
                *(const float4*)(B + (size_t)(kt + r) * N + col0 + c4);
        }
        __syncthreads();
#pragma unroll
        for (int k = 0; k < 16; k++) {
            float a[8], bb[8];
            *(float4*)(a)      = *(const float4*)&As[k][tRow * 8];
            *(float4*)(a + 4)  = *(const float4*)&As[k][tRow * 8 + 4];
            *(float4*)(bb)     = *(const float4*)&Bs[k][tCol * 8];
            *(float4*)(bb + 4) = *(const float4*)&Bs[k][tCol * 8 + 4];
#pragma unroll
            for (int i = 0; i < 8; i++)
#pragma unroll
                for (int j = 0; j < 8; j++)
                    acc[i][j] = fmaf(a[i], bb[j], acc[i][j]);
        }
        __syncthreads();
    }

#pragma unroll
    for (int i = 0; i < 8; i++) {
        int r = row0 + tRow * 8 + i;
#pragma unroll
        for (int j = 0; j < 8; j += 4) {
            int c = col0 + tCol * 8 + j;
            float4 v = make_float4(acc[i][j], acc[i][j+1], acc[i][j+2], acc[i][j+3]);
            if (EPI) {
                float4 uu = *(const float4*)(U + (size_t)r * N + c);
                float4 dd = *(const float4*)(Dv + c);
                v.x = fmaf(dd.x, uu.x, v.x); v.y = fmaf(dd.y, uu.y, v.y);
                v.z = fmaf(dd.z, uu.z, v.z); v.w = fmaf(dd.w, uu.w, v.w);
            }
            *(float4*)(C + (size_t)r * N + c) = v;
        }
    }
}

// ---------------- scan helpers ---------------------------------------------
__device__ __forceinline__ void elem_MF(const float* __restrict__ yrow, int p, float Aa,
                                        float& M11, float& M12, float& M21, float& M22,
                                        float& bur, float& bui, float& f1, float& f2) {
    float dt  = 1.f / (1.f + __expf(-yrow[p]));
    bur = yrow[PQ + p];
    bui = yrow[2 * PQ + p];
    float dtA = dt * Aa;
    float S   = 1.f / (1.f + dt * dtA);
    M11 = 1.f - dt * dtA * S;
    M12 = -dtA * S;
    M21 = dt * S;
    M22 = S;
    f1  = M11 * dt;
    f2  = M21 * dt;
}

// Pass A: per-chunk composed (A_acc, b_acc)
__global__ void scan_passA(const float* __restrict__ A_diag) {
    int t = blockIdx.x * blockDim.x + threadIdx.x;   // B*P*NCHUNK = 131072
    int p  = t & (PQ - 1);
    int ck = (t >> 8) & (NCHUNK - 1);
    int b  = t >> 14;
    float Aa = fmaxf(A_diag[p], 0.f);
    float a11 = 1.f, a12 = 0.f, a21 = 0.f, a22 = 1.f;
    float b1r = 0.f, b1i = 0.f, b2r = 0.f, b2i = 0.f;
    size_t base = (size_t)(b * LQ + ck * LC) * (3 * PQ);
    for (int i = 0; i < LC; i++) {
        const float* yrow = g_Y + base + (size_t)i * (3 * PQ);
        float M11, M12, M21, M22, bur, bui, f1, f2;
        elem_MF(yrow, p, Aa, M11, M12, M21, M22, bur, bui, f1, f2);
        float n11 = M11 * a11 + M12 * a21, n12 = M11 * a12 + M12 * a22;
        float n21 = M21 * a11 + M22 * a21, n22 = M21 * a12 + M22 * a22;
        a11 = n11; a12 = n12; a21 = n21; a22 = n22;
        float nb1r = M11 * b1r + M12 * b2r + f1 * bur;
        float nb1i = M11 * b1i + M12 * b2i + f1 * bui;
        float nb2r = M21 * b1r + M22 * b2r + f2 * bur;
        float nb2i = M21 * b1i + M22 * b2i + f2 * bui;
        b1r = nb1r; b1i = nb1i; b2r = nb2r; b2i = nb2i;
    }
    size_t cidx = ((size_t)(b * PQ + p) * NCHUNK + ck) * 8;
    g_chunk[cidx + 0] = a11; g_chunk[cidx + 1] = a12;
    g_chunk[cidx + 2] = a21; g_chunk[cidx + 3] = a22;
    g_chunk[cidx + 4] = b1r; g_chunk[cidx + 5] = b1i;
    g_chunk[cidx + 6] = b2r; g_chunk[cidx + 7] = b2i;
}

// Pass B: sequential scan over chunk summaries -> carry-in per chunk
__global__ void scan_passB() {
    int t = blockIdx.x * blockDim.x + threadIdx.x;   // B*P = 2048
    if (t >= BQ * PQ) return;
    float s1r = 0.f, s1i = 0.f, s2r = 0.f, s2i = 0.f;
    size_t cb = (size_t)t * NCHUNK;
    for (int k = 0; k < NCHUNK; k++) {
        float* cw = g_carry + (cb + k) * 4;
        cw[0] = s1r; cw[1] = s1i; cw[2] = s2r; cw[3] = s2i;
        const float* ch = g_chunk + (cb + k) * 8;
        float a11 = ch[0], a12 = ch[1], a21 = ch[2], a22 = ch[3];
        float n1r = a11 * s1r + a12 * s2r + ch[4];
        float n1i = a11 * s1i + a12 * s2i + ch[5];
        float n2r = a21 * s1r + a22 * s2r + ch[6];
        float n2i = a21 * s1i + a22 * s2i + ch[7];
        s1r = n1r; s1i = n1i; s2r = n2r; s2i = n2i;
    }
}

// Pass C: replay recurrence from carry, emit x (= state component 2) into g_X
__global__ void scan_passC(const float* __restrict__ A_diag) {
    int t = blockIdx.x * blockDim.x + threadIdx.x;
    int p  = t & (PQ - 1);
    int ck = (t >> 8) & (NCHUNK - 1);
    int b  = t >> 14;
    float Aa = fmaxf(A_diag[p], 0.f);
    size_t cidx = ((size_t)(b * PQ + p) * NCHUNK + ck) * 4;
    float s1r = g_carry[cidx + 0], s1i = g_carry[cidx + 1];
    float s2r = g_carry[cidx + 2], s2i = g_carry[cidx + 3];
    int row0 = b * LQ + ck * LC;
    size_t base = (size_t)row0 * (3 * PQ);
    for (int i = 0; i < LC; i++) {
        const float* yrow = g_Y + base + (size_t)i * (3 * PQ);
        float M11, M12, M21, M22, bur, bui, f1, f2;
        elem_MF(yrow, p, Aa, M11, M12, M21, M22, bur, bui, f1, f2);
        float n1r = M11 * s1r + M12 * s2r + f1 * bur;
        float n1i = M11 * s1i + M12 * s2i + f1 * bui;
        float n2r = M21 * s1r + M22 * s2r + f2 * bur;
        float n2i = M21 * s1i + M22 * s2i + f2 * bui;
        s1r = n1r; s1i = n1i; s2r = n2r; s2i = n2i;
        size_t xrow = (size_t)(row0 + i) * (2 * PQ);
        g_X[xrow + p]      = s2r;
        g_X[xrow + PQ + p] = s2i;
    }
}

// ---------------- launch ----------------------------------------------------
extern "C" void kernel_launch(void* const* d_in, const int* in_sizes, int n_in,
                              void* d_out, int out_size) {
    const float* u      = (const float*)d_in[0];
    const float* A_diag = (const float*)d_in[1];
    const float* B_re   = (const float*)d_in[2];
    const float* B_im   = (const float*)d_in[3];
    const float* C_re   = (const float*)d_in[4];
    const float* C_im   = (const float*)d_in[5];
    const float* D      = (const float*)d_in[6];
    const float* W_dt   = (const float*)d_in[7];
    float* out = (float*)d_out;

    float* Y = nullptr;  cudaGetSymbolAddress((void**)&Y, g_Y);
    float* X = nullptr;  cudaGetSymbolAddress((void**)&X, g_X);
    float* Wc = nullptr; cudaGetSymbolAddress((void**)&Wc, g_Wcat);
    float* Cc = nullptr; cudaGetSymbolAddress((void**)&Cc, g_Ccat);

    prep_wcat<<<(HQ * 3 * PQ + 255) / 256, 256>>>(W_dt, B_re, B_im);
    prep_ccat<<<(2 * PQ * HQ + 255) / 256, 256>>>(C_re, C_im);

    // GEMM1: Y[32768,768] = u[32768,768] @ Wcat[768,768]
    {
        dim3 grid(3 * PQ / 128, ROWS / 128);
        sgemm<false><<<grid, 256>>>(u, Wc, Y, ROWS, 3 * PQ, HQ, nullptr, nullptr);
    }

    // Scan
    scan_passA<<<(BQ * PQ * NCHUNK) / 256, 256>>>(A_diag);
    scan_passB<<<(BQ * PQ + 255) / 256, 256>>>();
    scan_passC<<<(BQ * PQ * NCHUNK) / 256, 256>>>(A_diag);

    // GEMM2: out[32768,768] = X[32768,512] @ Ccat[512,768] + D .* u
    {
        dim3 grid(HQ / 128, ROWS / 128);
        sgemm<true><<<grid, 256>>>(X, Cc, out, ROWS, HQ, 2 * PQ, D, u);
    }
}

// round 6
// speedup vs baseline: 2.7458x; 2.7458x over previous
#include <cuda_runtime.h>
#include <cstdint>

// Problem dims (fixed per reference)
#define BQ 8
#define LQ 4096
#define HQ 768
#define PQ 256
#define ROWS (BQ*LQ)        // 32768
#define LC 64               // scan chunk length
#define NCHUNK (LQ/LC)      // 64

// GEMM tiling
#define BM 128
#define BN 128
#define KC 32
#define NSTG 3
#define ASZ (BM*KC*4)       // 16 KB
#define BSZ (BN*KC*4)       // 16 KB
#define STG (ASZ+BSZ)       // 32 KB
#define GSMEM (NSTG*STG)    // 96 KB

// ---------------- scratch (__device__ globals) ------------------------------
__device__ float g_WcatT[3*PQ * HQ];             // [n=768][k=768] K-major, tf32-rounded
__device__ float g_CcatT[HQ * 2*PQ];             // [n=768][k=512] K-major, tf32-rounded
__device__ float g_Ru[(size_t)ROWS * HQ];        // tf32-rounded copy of u
__device__ float g_Y[(size_t)ROWS * 3 * PQ];     // dt-logit | Bu_re | Bu_im
__device__ float g_X[(size_t)ROWS * 2 * PQ];     // x_re | x_im (tf32-rounded)
__device__ float g_chunk[BQ * PQ * NCHUNK * 8];
__device__ float g_carry[BQ * PQ * NCHUNK * 4];

// ---------------- helpers ---------------------------------------------------
__device__ __forceinline__ uint32_t smem_u32(const void* p) {
    uint32_t a;
    asm("{ .reg .u64 t; cvta.to.shared.u64 t, %1; cvt.u32.u64 %0, t; }" : "=r"(a) : "l"(p));
    return a;
}
__device__ __forceinline__ float to_tf32(float x) {
    uint32_t u;
    asm("cvt.rna.tf32.f32 %0, %1;" : "=r"(u) : "f"(x));
    return __uint_as_float(u);
}
#define SWZ128(o) ((o) ^ (((o) >> 3) & 0x70))
__device__ __forceinline__ void cp16(uint32_t smem, const void* gmem) {
    asm volatile("cp.async.cg.shared.global [%0], [%1], 16;" :: "r"(smem), "l"(gmem) : "memory");
}
#define CP_COMMIT()  asm volatile("cp.async.commit_group;" ::: "memory")
#define CP_WAIT(n)   asm volatile("cp.async.wait_group %0;" :: "n"(n) : "memory")

#define LDSM_X4(r0,r1,r2,r3,addr) \
    asm volatile("ldmatrix.sync.aligned.m8n8.x4.shared.b16 {%0,%1,%2,%3}, [%4];" \
        : "=r"(r0),"=r"(r1),"=r"(r2),"=r"(r3) : "r"(addr))

#define MMA_TF32(c, a, b) \
    asm volatile("mma.sync.aligned.m16n8k8.row.col.f32.tf32.tf32.f32 " \
        "{%0,%1,%2,%3}, {%4,%5,%6,%7}, {%8,%9}, {%0,%1,%2,%3};" \
        : "+f"((c)[0]),"+f"((c)[1]),"+f"((c)[2]),"+f"((c)[3]) \
        : "r"((a)[0]),"r"((a)[1]),"r"((a)[2]),"r"((a)[3]), "r"((b)[0]),"r"((b)[1]))

// ---------------- prep kernels ----------------------------------------------
__global__ void round_u_k(const float4* __restrict__ in, float4* __restrict__ out, int n4) {
    int i = blockIdx.x * blockDim.x + threadIdx.x;
    if (i >= n4) return;
    float4 v = in[i];
    v.x = to_tf32(v.x); v.y = to_tf32(v.y); v.z = to_tf32(v.z); v.w = to_tf32(v.w);
    out[i] = v;
}

// g_WcatT[n][h]: n<256 -> W_dt[h][n]; 256..511 -> B_re[n-256][h]; else B_im[n-512][h]
__global__ void prep_wcatT(const float* __restrict__ W_dt,
                           const float* __restrict__ B_re,
                           const float* __restrict__ B_im) {
    int idx = blockIdx.x * blockDim.x + threadIdx.x;
    if (idx >= 3 * PQ * HQ) return;
    int n = idx / HQ;
    int h = idx % HQ;
    float v;
    if (n < PQ)            v = W_dt[(size_t)h * PQ + n];
    else if (n < 2 * PQ)   v = B_re[(size_t)(n - PQ) * HQ + h];
    else                   v = B_im[(size_t)(n - 2 * PQ) * HQ + h];
    g_WcatT[idx] = to_tf32(v);
}
// g_CcatT[h][k]: k<256 -> C_re[h][k]; else -C_im[h][k-256]
__global__ void prep_ccatT(const float* __restrict__ C_re,
                           const float* __restrict__ C_im) {
    int idx = blockIdx.x * blockDim.x + threadIdx.x;
    if (idx >= HQ * 2 * PQ) return;
    int h = idx / (2 * PQ);
    int k = idx % (2 * PQ);
    float v = (k < PQ) ? C_re[(size_t)h * PQ + k] : -C_im[(size_t)h * PQ + (k - PQ)];
    g_CcatT[idx] = to_tf32(v);
}

// ---------------- tf32 mma.sync GEMM: C[M,N] = A[M,K] @ Bt[N,K]^T (+ D.*U) --
// A, Bt: fp32 (tf32-prerounded), K-major. Tile 128x128, 8 warps (2x4), KC=32.
template<bool EPI>
__global__ __launch_bounds__(256, 2)
void gemm_mma(const float* __restrict__ A, const float* __restrict__ Bt,
              float* __restrict__ C, int M, int N, int K,
              const float* __restrict__ Dv, const float* __restrict__ U) {
    extern __shared__ char smem[];
    const uint32_t sb = smem_u32(smem);
    const int tid = threadIdx.x;
    const int wid = tid >> 5, lane = tid & 31;
    const int m0 = blockIdx.y * BM, n0 = blockIdx.x * BN;
    const int wm = wid >> 2, wn = wid & 3;     // 2 x 4 warp grid
    const int NS = K / KC;

    // ldmatrix per-thread address components
    const int t7 = lane & 7, jq = lane >> 3;
    const uint32_t swmask = (uint32_t)t7 << 4;
    const int rowA = (jq & 1) * 8 + t7;  // A: {m0..7@g0, m8..15@g0, m0..7@g1, m8..15@g1}
    const int kgA  = jq >> 1;
    const int rowB = (jq >> 1) * 8 + t7; // B: {n0..7@g0, n0..7@g1, n8..15@g0, n8..15@g1}
    const int kgB  = jq & 1;

    auto stage = [&](int s) {
        uint32_t buf = sb + (uint32_t)(s % NSTG) * STG;
        int kt = s * KC;
#pragma unroll
        for (int i = 0; i < 4; i++) {
            int c = tid + i * 256;             // 1024 16B chunks for A
            int r = c >> 3, k4 = c & 7;
            cp16(buf + SWZ128(r * 128 + k4 * 16), A + (size_t)(m0 + r) * K + kt + k4 * 4);
        }
#pragma unroll
        for (int i = 0; i < 4; i++) {
            int c = tid + i * 256;             // 1024 for B
            int r = c >> 3, k4 = c & 7;
            cp16(buf + ASZ + SWZ128(r * 128 + k4 * 16), Bt + (size_t)(n0 + r) * K + kt + k4 * 4);
        }
        CP_COMMIT();
    };

    float acc[4][4][4];
#pragma unroll
    for (int i = 0; i < 4; i++)
#pragma unroll
        for (int j = 0; j < 4; j++)
#pragma unroll
            for (int v = 0; v < 4; v++) acc[i][j][v] = 0.f;

    stage(0);
    stage(1);

    for (int s = 0; s < NS; s++) {
        if (s < NS - 1) { CP_WAIT(1); } else { CP_WAIT(0); }
        __syncthreads();
        uint32_t ab = sb + (uint32_t)(s % NSTG) * STG;
        uint32_t bb = ab + ASZ;
#pragma unroll
        for (int q = 0; q < 4; q++) {          // 4 x k8 within KC=32
            uint32_t af[4][4];
#pragma unroll
            for (int i = 0; i < 4; i++) {
                uint32_t ad = ab + (uint32_t)((wm * 64 + i * 16 + rowA) * 128)
                                 + ((uint32_t)((q * 2 + kgA) * 16) ^ swmask);
                LDSM_X4(af[i][0], af[i][1], af[i][2], af[i][3], ad);
            }
            uint32_t bf[4][2];
#pragma unroll
            for (int np = 0; np < 2; np++) {
                uint32_t bd = bb + (uint32_t)((wn * 32 + np * 16 + rowB) * 128)
                                 + ((uint32_t)((q * 2 + kgB) * 16) ^ swmask);
                LDSM_X4(bf[np*2][0], bf[np*2][1], bf[np*2+1][0], bf[np*2+1][1], bd);
            }
#pragma unroll
            for (int i = 0; i < 4; i++)
#pragma unroll
                for (int jn = 0; jn < 4; jn++)
                    MMA_TF32(acc[i][jn], af[i], bf[jn]);
        }
        __syncthreads();
        if (s + NSTG - 1 < NS) stage(s + NSTG - 1);
    }

    // epilogue: fragment (gr, gc) -> rows +0/+8, cols pair
    const int gr = lane >> 2, gc = (lane & 3) * 2;
#pragma unroll
    for (int i = 0; i < 4; i++) {
        int r = m0 + wm * 64 + i * 16 + gr;
#pragma unroll
        for (int jn = 0; jn < 4; jn++) {
            int c = n0 + wn * 32 + jn * 8 + gc;
            float2 v0 = make_float2(acc[i][jn][0], acc[i][jn][1]);
            float2 v1 = make_float2(acc[i][jn][2], acc[i][jn][3]);
            if (EPI) {
                float2 dd = *(const float2*)(Dv + c);
                float2 u0 = *(const float2*)(U + (size_t)r * N + c);
                float2 u1 = *(const float2*)(U + (size_t)(r + 8) * N + c);
                v0.x = fmaf(dd.x, u0.x, v0.x); v0.y = fmaf(dd.y, u0.y, v0.y);
                v1.x = fmaf(dd.x, u1.x, v1.x); v1.y = fmaf(dd.y, u1.y, v1.y);
            }
            *(float2*)(C + (size_t)r * N + c)       = v0;
            *(float2*)(C + (size_t)(r + 8) * N + c) = v1;
        }
    }
}

// ---------------- scan ------------------------------------------------------
__device__ __forceinline__ void elem_MF(const float* __restrict__ yrow, int p, float Aa,
                                        float& M11, float& M12, float& M21, float& M22,
                                        float& bur, float& bui, float& f1, float& f2) {
    float dt  = 1.f / (1.f + __expf(-yrow[p]));
    bur = yrow[PQ + p];
    bui = yrow[2 * PQ + p];
    float dtA = dt * Aa;
    float S   = 1.f / (1.f + dt * dtA);
    M11 = 1.f - dt * dtA * S;
    M12 = -dtA * S;
    M21 = dt * S;
    M22 = S;
    f1  = M11 * dt;
    f2  = M21 * dt;
}

__global__ void scan_passA(const float* __restrict__ A_diag) {
    int t = blockIdx.x * blockDim.x + threadIdx.x;
    int p  = t & (PQ - 1);
    int ck = (t >> 8) & (NCHUNK - 1);
    int b  = t >> 14;
    float Aa = fmaxf(A_diag[p], 0.f);
    float a11 = 1.f, a12 = 0.f, a21 = 0.f, a22 = 1.f;
    float b1r = 0.f, b1i = 0.f, b2r = 0.f, b2i = 0.f;
    size_t base = (size_t)(b * LQ + ck * LC) * (3 * PQ);
    for (int i = 0; i < LC; i++) {
        const float* yrow = g_Y + base + (size_t)i * (3 * PQ);
        float M11, M12, M21, M22, bur, bui, f1, f2;
        elem_MF(yrow, p, Aa, M11, M12, M21, M22, bur, bui, f1, f2);
        float n11 = M11 * a11 + M12 * a21, n12 = M11 * a12 + M12 * a22;
        float n21 = M21 * a11 + M22 * a21, n22 = M21 * a12 + M22 * a22;
        a11 = n11; a12 = n12; a21 = n21; a22 = n22;
        float nb1r = M11 * b1r + M12 * b2r + f1 * bur;
        float nb1i = M11 * b1i + M12 * b2i + f1 * bui;
        float nb2r = M21 * b1r + M22 * b2r + f2 * bur;
        float nb2i = M21 * b1i + M22 * b2i + f2 * bui;
        b1r = nb1r; b1i = nb1i; b2r = nb2r; b2i = nb2i;
    }
    size_t cidx = ((size_t)(b * PQ + p) * NCHUNK + ck) * 8;
    g_chunk[cidx + 0] = a11; g_chunk[cidx + 1] = a12;
    g_chunk[cidx + 2] = a21; g_chunk[cidx + 3] = a22;
    g_chunk[cidx + 4] = b1r; g_chunk[cidx + 5] = b1i;
    g_chunk[cidx + 6] = b2r; g_chunk[cidx + 7] = b2i;
}

__global__ void scan_passB() {
    int t = blockIdx.x * blockDim.x + threadIdx.x;
    if (t >= BQ * PQ) return;
    float s1r = 0.f, s1i = 0.f, s2r = 0.f, s2i = 0.f;
    size_t cb = (size_t)t * NCHUNK;
    for (int k = 0; k < NCHUNK; k++) {
        float* cw = g_carry + (cb + k) * 4;
        cw[0] = s1r; cw[1] = s1i; cw[2] = s2r; cw[3] = s2i;
        const float* ch = g_chunk + (cb + k) * 8;
        float a11 = ch[0], a12 = ch[1], a21 = ch[2], a22 = ch[3];
        float n1r = a11 * s1r + a12 * s2r + ch[4];
        float n1i = a11 * s1i + a12 * s2i + ch[5];
        float n2r = a21 * s1r + a22 * s2r + ch[6];
        float n2i = a21 * s1i + a22 * s2i + ch[7];
        s1r = n1r; s1i = n1i; s2r = n2r; s2i = n2i;
    }
}

__global__ void scan_passC(const float* __restrict__ A_diag) {
    int t = blockIdx.x * blockDim.x + threadIdx.x;
    int p  = t & (PQ - 1);
    int ck = (t >> 8) & (NCHUNK - 1);
    int b  = t >> 14;
    float Aa = fmaxf(A_diag[p], 0.f);
    size_t cidx = ((size_t)(b * PQ + p) * NCHUNK + ck) * 4;
    float s1r = g_carry[cidx + 0], s1i = g_carry[cidx + 1];
    float s2r = g_carry[cidx + 2], s2i = g_carry[cidx + 3];
    int row0 = b * LQ + ck * LC;
    size_t base = (size_t)row0 * (3 * PQ);
    for (int i = 0; i < LC; i++) {
        const float* yrow = g_Y + base + (size_t)i * (3 * PQ);
        float M11, M12, M21, M22, bur, bui, f1, f2;
        elem_MF(yrow, p, Aa, M11, M12, M21, M22, bur, bui, f1, f2);
        float n1r = M11 * s1r + M12 * s2r + f1 * bur;
        float n1i = M11 * s1i + M12 * s2i + f1 * bui;
        float n2r = M21 * s1r + M22 * s2r + f2 * bur;
        float n2i = M21 * s1i + M22 * s2i + f2 * bui;
        s1r = n1r; s1i = n1i; s2r = n2r; s2i = n2i;
        size_t xrow = (size_t)(row0 + i) * (2 * PQ);
        g_X[xrow + p]      = to_tf32(s2r);   // tf32-round for GEMM2 A-operand
        g_X[xrow + PQ + p] = to_tf32(s2i);
    }
}

// ---------------- launch ----------------------------------------------------
extern "C" void kernel_launch(void* const* d_in, const int* in_sizes, int n_in,
                              void* d_out, int out_size) {
    const float* u      = (const float*)d_in[0];
    const float* A_diag = (const float*)d_in[1];
    const float* B_re   = (const float*)d_in[2];
    const float* B_im   = (const float*)d_in[3];
    const float* C_re   = (const float*)d_in[4];
    const float* C_im   = (const float*)d_in[5];
    const float* D      = (const float*)d_in[6];
    const float* W_dt   = (const float*)d_in[7];
    float* out = (float*)d_out;

    float* Y  = nullptr; cudaGetSymbolAddress((void**)&Y,  g_Y);
    float* X  = nullptr; cudaGetSymbolAddress((void**)&X,  g_X);
    float* Wt = nullptr; cudaGetSymbolAddress((void**)&Wt, g_WcatT);
    float* Ct = nullptr; cudaGetSymbolAddress((void**)&Ct, g_CcatT);
    float* Ru = nullptr; cudaGetSymbolAddress((void**)&Ru, g_Ru);

    cudaFuncSetAttribute(gemm_mma<false>, cudaFuncAttributeMaxDynamicSharedMemorySize, GSMEM);
    cudaFuncSetAttribute(gemm_mma<true>,  cudaFuncAttributeMaxDynamicSharedMemorySize, GSMEM);

    prep_wcatT<<<(3 * PQ * HQ + 255) / 256, 256>>>(W_dt, B_re, B_im);
    prep_ccatT<<<(HQ * 2 * PQ + 255) / 256, 256>>>(C_re, C_im);
    {
        int n4 = ROWS * HQ / 4;
        round_u_k<<<(n4 + 255) / 256, 256>>>((const float4*)u, (float4*)Ru, n4);
    }

    // GEMM1: Y[32768,768] = Ru @ WcatT^T
    {
        dim3 grid(3 * PQ / BN, ROWS / BM);
        gemm_mma<false><<<grid, 256, GSMEM>>>(Ru, Wt, Y, ROWS, 3 * PQ, HQ, nullptr, nullptr);
    }

    // Scan
    scan_passA<<<(BQ * PQ * NCHUNK) / 256, 256>>>(A_diag);
    scan_passB<<<(BQ * PQ + 255) / 256, 256>>>();
    scan_passC<<<(BQ * PQ * NCHUNK) / 256, 256>>>(A_diag);

    // GEMM2: out = X @ CcatT^T + D .* u  (u at full precision in epilogue)
    {
        dim3 grid(HQ / BN, ROWS / BM);
        gemm_mma<true><<<grid, 256, GSMEM>>>(X, Ct, out, ROWS, HQ, 2 * PQ, D, u);
    }
}

// round 7
// speedup vs baseline: 3.6374x; 1.3247x over previous
#include <cuda_runtime.h>
#include <cuda_fp16.h>
#include <cstdint>

// Problem dims (fixed per reference)
#define BQ 8
#define LQ 4096
#define HQ 768
#define PQ 256
#define ROWS (BQ*LQ)        // 32768
#define LC 64               // scan chunk length
#define NCHUNK (LQ/LC)      // 64

// GEMM tiling (fp16 operands)
#define BM 128
#define BN 128
#define KC 64               // halfs per stage-row = 128 bytes
#define NSTG 3
#define ASZ (BM*KC*2)       // 16 KB
#define BSZ (BN*KC*2)       // 16 KB
#define STG (ASZ+BSZ)       // 32 KB
#define GSMEM (NSTG*STG)    // 96 KB

// ---------------- scratch (__device__ globals) ------------------------------
__device__ __half g_Wh[3*PQ * HQ];               // [n=768][k=768] K-major fp16
__device__ __half g_Ch[HQ * 2*PQ];               // [n=768][k=512] K-major fp16
__device__ __half g_uh[(size_t)ROWS * HQ];       // fp16 copy of u
__device__ float  g_Y[(size_t)ROWS * 3 * PQ];    // dt-logit | Bu_re | Bu_im (fp32)
__device__ __half g_Xh[(size_t)ROWS * 2 * PQ];   // x_re | x_im (fp16)
__device__ float  g_chunk[BQ * PQ * NCHUNK * 8];
__device__ float  g_carry[BQ * PQ * NCHUNK * 4];

// ---------------- helpers ---------------------------------------------------
__device__ __forceinline__ uint32_t smem_u32(const void* p) {
    uint32_t a;
    asm("{ .reg .u64 t; cvta.to.shared.u64 t, %1; cvt.u32.u64 %0, t; }" : "=r"(a) : "l"(p));
    return a;
}
__device__ __forceinline__ void cp16(uint32_t smem, const void* gmem) {
    asm volatile("cp.async.cg.shared.global [%0], [%1], 16;" :: "r"(smem), "l"(gmem) : "memory");
}
#define CP_COMMIT()  asm volatile("cp.async.commit_group;" ::: "memory")
#define CP_WAIT(n)   asm volatile("cp.async.wait_group %0;" :: "n"(n) : "memory")

#define LDSM_X4(r0,r1,r2,r3,addr) \
    asm volatile("ldmatrix.sync.aligned.m8n8.x4.shared.b16 {%0,%1,%2,%3}, [%4];" \
        : "=r"(r0),"=r"(r1),"=r"(r2),"=r"(r3) : "r"(addr))

#define MMA_F16(c, a, b) \
    asm volatile("mma.sync.aligned.m16n8k16.row.col.f32.f16.f16.f32 " \
        "{%0,%1,%2,%3}, {%4,%5,%6,%7}, {%8,%9}, {%0,%1,%2,%3};" \
        : "+f"((c)[0]),"+f"((c)[1]),"+f"((c)[2]),"+f"((c)[3]) \
        : "r"((a)[0]),"r"((a)[1]),"r"((a)[2]),"r"((a)[3]), "r"((b)[0]),"r"((b)[1]))

// ---------------- prep kernels ----------------------------------------------
__global__ void convert_u(const float4* __restrict__ in, __half2* __restrict__ out, int n4) {
    int i = blockIdx.x * blockDim.x + threadIdx.x;
    if (i >= n4) return;
    float4 v = in[i];
    out[2*i]   = __floats2half2_rn(v.x, v.y);
    out[2*i+1] = __floats2half2_rn(v.z, v.w);
}

// g_Wh[n][h]: n<256 -> W_dt[h][n]; 256..511 -> B_re[n-256][h]; else B_im[n-512][h]
__global__ void prep_wcatT(const float* __restrict__ W_dt,
                           const float* __restrict__ B_re,
                           const float* __restrict__ B_im) {
    int idx = blockIdx.x * blockDim.x + threadIdx.x;
    if (idx >= 3 * PQ * HQ) return;
    int n = idx / HQ;
    int h = idx % HQ;
    float v;
    if (n < PQ)            v = W_dt[(size_t)h * PQ + n];
    else if (n < 2 * PQ)   v = B_re[(size_t)(n - PQ) * HQ + h];
    else                   v = B_im[(size_t)(n - 2 * PQ) * HQ + h];
    g_Wh[idx] = __float2half_rn(v);
}
// g_Ch[h][k]: k<256 -> C_re[h][k]; else -C_im[h][k-256]
__global__ void prep_ccatT(const float* __restrict__ C_re,
                           const float* __restrict__ C_im) {
    int idx = blockIdx.x * blockDim.x + threadIdx.x;
    if (idx >= HQ * 2 * PQ) return;
    int h = idx / (2 * PQ);
    int k = idx % (2 * PQ);
    float v = (k < PQ) ? C_re[(size_t)h * PQ + k] : -C_im[(size_t)h * PQ + (k - PQ)];
    g_Ch[idx] = __float2half_rn(v);
}

// ---------------- fp16 mma.sync GEMM: C[M,N] = A[M,K] @ Bt[N,K]^T -----------
// A, Bt fp16 K-major. Tile 128x128, 8 warps (2x4, warp tile 64x32), KC=64.
// EPI=false: write __half. EPI=true: write float with + D.*U (U fp16).
template<bool EPI>
__global__ __launch_bounds__(256, 2)
void gemm_h(const __half* __restrict__ A, const __half* __restrict__ Bt,
            void* __restrict__ Cout, int M, int N, int K,
            const float* __restrict__ Dv, const __half* __restrict__ U) {
    extern __shared__ char smem[];
    const uint32_t sb = smem_u32(smem);
    const int tid = threadIdx.x;
    const int wid = tid >> 5, lane = tid & 31;
    const int m0 = blockIdx.y * BM, n0 = blockIdx.x * BN;
    const int wm = wid >> 2, wn = wid & 3;     // 2 x 4 warp grid
    const int NS = K / KC;

    // ldmatrix per-thread address components (8x8 b16 matrices, 128B rows)
    const int t7 = lane & 7, jq = lane >> 3;
    const uint32_t swmask = (uint32_t)t7 << 4;
    const int rowA = (jq & 1) * 8 + t7;        // matrices: m0-7/k0-7, m8-15/k0-7, m0-7/k8-15, m8-15/k8-15
    const int kgA  = jq >> 1;
    const int rowB = (jq >> 1) * 8 + t7;       // matrices: n0-7/k0-7, n0-7/k8-15, n8-15/k0-7, n8-15/k8-15
    const int kgB  = jq & 1;

    auto stage = [&](int s) {
        uint32_t buf = sb + (uint32_t)(s % NSTG) * STG;
        int kt = s * KC;
#pragma unroll
        for (int i = 0; i < 4; i++) {
            int c = tid + i * 256;             // 1024 16B chunks for A (128 rows x 8)
            int r = c >> 3, k8 = c & 7;
            uint32_t off = (uint32_t)(k8 * 16) ^ ((uint32_t)(r & 7) << 4);
            cp16(buf + (uint32_t)r * 128 + off, A + (size_t)(m0 + r) * K + kt + k8 * 8);
        }
#pragma unroll
        for (int i = 0; i < 4; i++) {
            int c = tid + i * 256;             // 1024 for B
            int r = c >> 3, k8 = c & 7;
            uint32_t off = (uint32_t)(k8 * 16) ^ ((uint32_t)(r & 7) << 4);
            cp16(buf + ASZ + (uint32_t)r * 128 + off, Bt + (size_t)(n0 + r) * K + kt + k8 * 8);
        }
        CP_COMMIT();
    };

    float acc[4][4][4];
#pragma unroll
    for (int i = 0; i < 4; i++)
#pragma unroll
        for (int j = 0; j < 4; j++)
#pragma unroll
            for (int v = 0; v < 4; v++) acc[i][j][v] = 0.f;

    stage(0);
    stage(1);

    for (int s = 0; s < NS; s++) {
        if (s < NS - 1) { CP_WAIT(1); } else { CP_WAIT(0); }
        __syncthreads();
        uint32_t ab = sb + (uint32_t)(s % NSTG) * STG;
        uint32_t bb = ab + ASZ;
#pragma unroll
        for (int q = 0; q < 4; q++) {          // 4 x k16 within KC=64; k16 block = 32 bytes
            uint32_t af[4][4];
#pragma unroll
            for (int i = 0; i < 4; i++) {      // 4 m16 tiles (warp rows 64)
                uint32_t ad = ab + (uint32_t)((wm * 64 + i * 16 + rowA) * 128)
                                 + ((uint32_t)(q * 32 + kgA * 16) ^ swmask);
                LDSM_X4(af[i][0], af[i][1], af[i][2], af[i][3], ad);
            }
            uint32_t bf[4][2];
#pragma unroll
            for (int np = 0; np < 2; np++) {   // 2 n16 groups (warp cols 32)
                uint32_t bd = bb + (uint32_t)((wn * 32 + np * 16 + rowB) * 128)
                                 + ((uint32_t)(q * 32 + kgB * 16) ^ swmask);
                LDSM_X4(bf[np*2][0], bf[np*2][1], bf[np*2+1][0], bf[np*2+1][1], bd);
            }
#pragma unroll
            for (int i = 0; i < 4; i++)
#pragma unroll
                for (int jn = 0; jn < 4; jn++)
                    MMA_F16(acc[i][jn], af[i], bf[jn]);
        }
        // NOTE: no barrier needed here — stage(s+2) writes buffer (s-1)%3 whose
        // readers all passed the barrier at the top of this iteration.
        if (s + NSTG - 1 < NS) stage(s + NSTG - 1);
    }

    // epilogue: fragment thread (gr, gc) -> rows +0/+8, col pair gc,gc+1
    const int gr = lane >> 2, gc = (lane & 3) * 2;
#pragma unroll
    for (int i = 0; i < 4; i++) {
        int r = m0 + wm * 64 + i * 16 + gr;
#pragma unroll
        for (int jn = 0; jn < 4; jn++) {
            int c = n0 + wn * 32 + jn * 8 + gc;
            if (EPI) {
                float* C = (float*)Cout;
                float2 v0 = make_float2(acc[i][jn][0], acc[i][jn][1]);
                float2 v1 = make_float2(acc[i][jn][2], acc[i][jn][3]);
                float2 dd = *(const float2*)(Dv + c);
                __half2 uh0 = *(const __half2*)(U + (size_t)r * N + c);
                __half2 uh1 = *(const __half2*)(U + (size_t)(r + 8) * N + c);
                float2 u0 = __half22float2(uh0), u1 = __half22float2(uh1);
                v0.x = fmaf(dd.x, u0.x, v0.x); v0.y = fmaf(dd.y, u0.y, v0.y);
                v1.x = fmaf(dd.x, u1.x, v1.x); v1.y = fmaf(dd.y, u1.y, v1.y);
                *(float2*)(C + (size_t)r * N + c)       = v0;
                *(float2*)(C + (size_t)(r + 8) * N + c) = v1;
            } else {
                float* C = (float*)Cout;
                *(float2*)(C + (size_t)r * N + c) =
                    make_float2(acc[i][jn][0], acc[i][jn][1]);
                *(float2*)(C + (size_t)(r + 8) * N + c) =
                    make_float2(acc[i][jn][2], acc[i][jn][3]);
            }
        }
    }
}

// ---------------- scan (fp32, reads g_Y) ------------------------------------
__device__ __forceinline__ void elem_MF(const float* __restrict__ yrow, int p, float Aa,
                                        float& M11, float& M12, float& M21, float& M22,
                                        float& bur, float& bui, float& f1, float& f2) {
    float dt  = 1.f / (1.f + __expf(-yrow[p]));
    bur = yrow[PQ + p];
    bui = yrow[2 * PQ + p];
    float dtA = dt * Aa;
    float S   = 1.f / (1.f + dt * dtA);
    M11 = 1.f - dt * dtA * S;
    M12 = -dtA * S;
    M21 = dt * S;
    M22 = S;
    f1  = M11 * dt;
    f2  = M21 * dt;
}

__global__ void scan_passA(const float* __restrict__ A_diag) {
    int t = blockIdx.x * blockDim.x + threadIdx.x;
    int p  = t & (PQ - 1);
    int ck = (t >> 8) & (NCHUNK - 1);
    int b  = t >> 14;
    float Aa = fmaxf(A_diag[p], 0.f);
    float a11 = 1.f, a12 = 0.f, a21 = 0.f, a22 = 1.f;
    float b1r = 0.f, b1i = 0.f, b2r = 0.f, b2i = 0.f;
    size_t base = (size_t)(b * LQ + ck * LC) * (3 * PQ);
    for (int i = 0; i < LC; i++) {
        const float* yrow = g_Y + base + (size_t)i * (3 * PQ);
        float M11, M12, M21, M22, bur, bui, f1, f2;
        elem_MF(yrow, p, Aa, M11, M12, M21, M22, bur, bui, f1, f2);
        float n11 = M11 * a11 + M12 * a21, n12 = M11 * a12 + M12 * a22;
        float n21 = M21 * a11 + M22 * a21, n22 = M21 * a12 + M22 * a22;
        a11 = n11; a12 = n12; a21 = n21; a22 = n22;
        float nb1r = M11 * b1r + M12 * b2r + f1 * bur;
        float nb1i = M11 * b1i + M12 * b2i + f1 * bui;
        float nb2r = M21 * b1r + M22 * b2r + f2 * bur;
        float nb2i = M21 * b1i + M22 * b2i + f2 * bui;
        b1r = nb1r; b1i = nb1i; b2r = nb2r; b2i = nb2i;
    }
    size_t cidx = ((size_t)(b * PQ + p) * NCHUNK + ck) * 8;
    g_chunk[cidx + 0] = a11; g_chunk[cidx + 1] = a12;
    g_chunk[cidx + 2] = a21; g_chunk[cidx + 3] = a22;
    g_chunk[cidx + 4] = b1r; g_chunk[cidx + 5] = b1i;
    g_chunk[cidx + 6] = b2r; g_chunk[cidx + 7] = b2i;
}

__global__ void scan_passB() {
    int t = blockIdx.x * blockDim.x + threadIdx.x;
    if (t >= BQ * PQ) return;
    float s1r = 0.f, s1i = 0.f, s2r = 0.f, s2i = 0.f;
    size_t cb = (size_t)t * NCHUNK;
    for (int k = 0; k < NCHUNK; k++) {
        float* cw = g_carry + (cb + k) * 4;
        cw[0] = s1r; cw[1] = s1i; cw[2] = s2r; cw[3] = s2i;
        const float* ch = g_chunk + (cb + k) * 8;
        float a11 = ch[0], a12 = ch[1], a21 = ch[2], a22 = ch[3];
        float n1r = a11 * s1r + a12 * s2r + ch[4];
        float n1i = a11 * s1i + a12 * s2i + ch[5];
        float n2r = a21 * s1r + a22 * s2r + ch[6];
        float n2i = a21 * s1i + a22 * s2i + ch[7];
        s1r = n1r; s1i = n1i; s2r = n2r; s2i = n2i;
    }
}

__global__ void scan_passC(const float* __restrict__ A_diag) {
    int t = blockIdx.x * blockDim.x + threadIdx.x;
    int p  = t & (PQ - 1);
    int ck = (t >> 8) & (NCHUNK - 1);
    int b  = t >> 14;
    float Aa = fmaxf(A_diag[p], 0.f);
    size_t cidx = ((size_t)(b * PQ + p) * NCHUNK + ck) * 4;
    float s1r = g_carry[cidx + 0], s1i = g_carry[cidx + 1];
    float s2r = g_carry[cidx + 2], s2i = g_carry[cidx + 3];
    int row0 = b * LQ + ck * LC;
    size_t base = (size_t)row0 * (3 * PQ);
    for (int i = 0; i < LC; i++) {
        const float* yrow = g_Y + base + (size_t)i * (3 * PQ);
        float M11, M12, M21, M22, bur, bui, f1, f2;
        elem_MF(yrow, p, Aa, M11, M12, M21, M22, bur, bui, f1, f2);
        float n1r = M11 * s1r + M12 * s2r + f1 * bur;
        float n1i = M11 * s1i + M12 * s2i + f1 * bui;
        float n2r = M21 * s1r + M22 * s2r + f2 * bur;
        float n2i = M21 * s1i + M22 * s2i + f2 * bui;
        s1r = n1r; s1i = n1i; s2r = n2r; s2i = n2i;
        size_t xrow = (size_t)(row0 + i) * (2 * PQ);
        g_Xh[xrow + p]      = __float2half_rn(s2r);
        g_Xh[xrow + PQ + p] = __float2half_rn(s2i);
    }
}

// ---------------- launch ----------------------------------------------------
extern "C" void kernel_launch(void* const* d_in, const int* in_sizes, int n_in,
                              void* d_out, int out_size) {
    const float* u      = (const float*)d_in[0];
    const float* A_diag = (const float*)d_in[1];
    const float* B_re   = (const float*)d_in[2];
    const float* B_im   = (const float*)d_in[3];
    const float* C_re   = (const float*)d_in[4];
    const float* C_im   = (const float*)d_in[5];
    const float* D      = (const float*)d_in[6];
    const float* W_dt   = (const float*)d_in[7];
    float* out = (float*)d_out;

    float*  Y  = nullptr; cudaGetSymbolAddress((void**)&Y,  g_Y);
    __half* Xh = nullptr; cudaGetSymbolAddress((void**)&Xh, g_Xh);
    __half* Wh = nullptr; cudaGetSymbolAddress((void**)&Wh, g_Wh);
    __half* Ch = nullptr; cudaGetSymbolAddress((void**)&Ch, g_Ch);
    __half* uh = nullptr; cudaGetSymbolAddress((void**)&uh, g_uh);

    cudaFuncSetAttribute(gemm_h<false>, cudaFuncAttributeMaxDynamicSharedMemorySize, GSMEM);
    cudaFuncSetAttribute(gemm_h<true>,  cudaFuncAttributeMaxDynamicSharedMemorySize, GSMEM);

    prep_wcatT<<<(3 * PQ * HQ + 255) / 256, 256>>>(W_dt, B_re, B_im);
    prep_ccatT<<<(HQ * 2 * PQ + 255) / 256, 256>>>(C_re, C_im);
    {
        int n4 = ROWS * HQ / 4;
        convert_u<<<(n4 + 255) / 256, 256>>>((const float4*)u, (__half2*)uh, n4);
    }

    // GEMM1: Y[32768,768] = uh @ Wh^T  (fp32 out)
    {
        dim3 grid(3 * PQ / BN, ROWS / BM);
        gemm_h<false><<<grid, 256, GSMEM>>>(uh, Wh, Y, ROWS, 3 * PQ, HQ, nullptr, nullptr);
    }

    // Scan
    scan_passA<<<(BQ * PQ * NCHUNK) / 256, 256>>>(A_diag);
    scan_passB<<<(BQ * PQ + 255) / 256, 256>>>();
    scan_passC<<<(BQ * PQ * NCHUNK) / 256, 256>>>(A_diag);

    // GEMM2: out = Xh @ Ch^T + D .* u  (fp32 out, u via fp16 copy)
    {
        dim3 grid(HQ / BN, ROWS / BM);
        gemm_h<true><<<grid, 256, GSMEM>>>(Xh, Ch, out, ROWS, HQ, 2 * PQ, D, uh);
    }
}